// round 1
// baseline (speedup 1.0000x reference)
#include <cuda_runtime.h>
#include <math.h>

#define NPTS 8192
#define CF   64
#define NH   4
#define KNN  16
#define DHD  16
#define NCHUNK 8
#define CHUNK  1024

// ---------------- scratch (static device memory; no allocations) -------------
__device__ float g_xq[NPTS * CF];
__device__ float g_xk[NPTS * CF];
__device__ float g_xv[NPTS * CF];
__device__ float g_pd[NCHUNK * NPTS * KNN];
__device__ int   g_pi[NCHUNK * NPTS * KNN];
__device__ int   g_idx[NPTS * KNN];

// ---------------- KNN: partial top-16 per candidate chunk --------------------
__global__ void knn_part_kernel(const float* __restrict__ p) {
    __shared__ float sx[CHUNK], sy[CHUNK], sz[CHUNK];
    const int q    = blockIdx.x * blockDim.x + threadIdx.x;
    const int base = blockIdx.y * CHUNK;

    for (int f = threadIdx.x; f < CHUNK * 3; f += blockDim.x) {
        float v = p[base * 3 + f];
        int j = f / 3, c = f - 3 * j;
        if (c == 0) sx[j] = v; else if (c == 1) sy[j] = v; else sz[j] = v;
    }
    __syncthreads();

    const float qx = p[q * 3 + 0], qy = p[q * 3 + 1], qz = p[q * 3 + 2];

    float bd[KNN]; int bi[KNN];
#pragma unroll
    for (int t = 0; t < KNN; t++) { bd[t] = 3.402823466e38f; bi[t] = 0; }
    float curmax = 3.402823466e38f;
    int   maxpos = 0;

    for (int j = 0; j < CHUNK; j++) {
        float dx = qx - sx[j], dy = qy - sy[j], dz = qz - sz[j];
        float d = dx * dx;
        d = fmaf(dy, dy, d);
        d = fmaf(dz, dz, d);
        if (d < curmax) {
#pragma unroll
            for (int t = 0; t < KNN; t++)
                if (t == maxpos) { bd[t] = d; bi[t] = base + j; }
            curmax = -1.0f;
#pragma unroll
            for (int t = 0; t < KNN; t++)
                if (bd[t] > curmax) { curmax = bd[t]; maxpos = t; }
        }
    }
    const int o = (blockIdx.y * NPTS + q) * KNN;
#pragma unroll
    for (int t = 0; t < KNN; t++) { g_pd[o + t] = bd[t]; g_pi[o + t] = bi[t]; }
}

// ---------------- KNN: merge 8x16 partials -> global top-16 ------------------
__global__ void knn_merge_kernel() {
    const int q = blockIdx.x * blockDim.x + threadIdx.x;
    float bd[KNN]; int bi[KNN];
#pragma unroll
    for (int t = 0; t < KNN; t++) { bd[t] = 3.402823466e38f; bi[t] = 0; }
    float curmax = 3.402823466e38f;
    int   maxpos = 0;

    for (int ch = 0; ch < NCHUNK; ch++) {
        const int o = (ch * NPTS + q) * KNN;
#pragma unroll
        for (int t = 0; t < KNN; t++) {
            float d = g_pd[o + t];
            int   i = g_pi[o + t];
            if (d < curmax) {
#pragma unroll
                for (int u = 0; u < KNN; u++)
                    if (u == maxpos) { bd[u] = d; bi[u] = i; }
                curmax = -1.0f;
#pragma unroll
                for (int u = 0; u < KNN; u++)
                    if (bd[u] > curmax) { curmax = bd[u]; maxpos = u; }
            }
        }
    }
#pragma unroll
    for (int t = 0; t < KNN; t++) g_idx[q * KNN + t] = bi[t];
}

// ---------------- xq/xk/xv = x @ {Wq,Wk,Wv} ---------------------------------
__global__ void qkv_gemm_kernel(const float* __restrict__ x,
                                const float* __restrict__ Wq,
                                const float* __restrict__ Wk,
                                const float* __restrict__ Wv) {
    __shared__ float Ws[CF * CF];
    __shared__ float xs[CF * CF];
    const float* W = (blockIdx.y == 0) ? Wq : ((blockIdx.y == 1) ? Wk : Wv);
    float* out = (blockIdx.y == 0) ? g_xq : ((blockIdx.y == 1) ? g_xk : g_xv);

    const int row0 = blockIdx.x * 64;
    const int tid  = threadIdx.y * 64 + threadIdx.x;
    for (int f = tid; f < CF * CF; f += 256) {
        Ws[f] = W[f];
        xs[f] = x[row0 * CF + f];
    }
    __syncthreads();

    const int c = threadIdx.x;
    for (int r = threadIdx.y; r < 64; r += 4) {
        float acc = 0.0f;
#pragma unroll
        for (int j = 0; j < CF; j++) acc = fmaf(xs[r * CF + j], Ws[j * CF + c], acc);
        out[(row0 + r) * CF + c] = acc;
    }
}

// ---------------- PPF angle helper ------------------------------------------
__device__ __forceinline__ float angle3(float ux, float uy, float uz,
                                        float vx, float vy, float vz) {
    float cx = uy * vz - uz * vy;
    float cy = uz * vx - ux * vz;
    float cz = ux * vy - uy * vx;
    float cn = sqrtf(cx * cx + cy * cy + cz * cz + 1e-9f);
    float dt = ux * vx + uy * vy + uz * vz;
    return atan2f(cn, dt);
}

// ---------------- Fused: PPF -> pe MLP -> attention -> Wo -> LN -> relu ------
__global__ void __launch_bounds__(64)
fused_attn_kernel(const float* __restrict__ p,
                  const float* __restrict__ x,
                  const float* __restrict__ normals,
                  const float* __restrict__ Wo,
                  const float* __restrict__ w1, const float* __restrict__ b1,
                  const float* __restrict__ w2, const float* __restrict__ b2,
                  const float* __restrict__ ln_g, const float* __restrict__ ln_b,
                  float* __restrict__ out) {
    const int n   = blockIdx.x;
    const int tid = threadIdx.x;

    __shared__ int   idx_s[KNN];
    __shared__ float ppf_s[KNN][4];
    __shared__ float pe1_s[KNN][CF];
    __shared__ float k_s[KNN][CF + 1];
    __shared__ float v_s[KNN][CF + 1];
    __shared__ float q_s[CF];
    __shared__ float o_s[CF];
    __shared__ float attn_s[NH * KNN];
    __shared__ float red_s[4];

    if (tid < KNN) idx_s[tid] = g_idx[n * KNN + tid];
    q_s[tid] = g_xq[n * CF + tid];
    __syncthreads();

    // PPF features: one thread per neighbor
    if (tid < KNN) {
        const int j = idx_s[tid];
        float px = p[3 * n], py = p[3 * n + 1], pz = p[3 * n + 2];
        float dx = p[3 * j] - px, dy = p[3 * j + 1] - py, dz = p[3 * j + 2] - pz;
        float ncx = normals[3 * n], ncy = normals[3 * n + 1], ncz = normals[3 * n + 2];
        float nrx = normals[3 * j], nry = normals[3 * j + 1], nrz = normals[3 * j + 2];
        ppf_s[tid][0] = angle3(ncx, ncy, ncz, dx, dy, dz);
        ppf_s[tid][1] = angle3(nrx, nry, nrz, dx, dy, dz);
        ppf_s[tid][2] = angle3(ncx, ncy, ncz, nrx, nry, nrz);
        ppf_s[tid][3] = sqrtf(dx * dx + dy * dy + dz * dz + 1e-9f);
    }
    __syncthreads();

    // pe layer 1: pe1[k][c] = relu(b1[c] + sum_j ppf[k][j] * w1[j][c])
    {
        float w0 = __ldg(&w1[0 * CF + tid]);
        float wa = __ldg(&w1[1 * CF + tid]);
        float wb = __ldg(&w1[2 * CF + tid]);
        float wc = __ldg(&w1[3 * CF + tid]);
        float bb = __ldg(&b1[tid]);
#pragma unroll
        for (int k = 0; k < KNN; k++) {
            float v = bb;
            v = fmaf(ppf_s[k][0], w0, v);
            v = fmaf(ppf_s[k][1], wa, v);
            v = fmaf(ppf_s[k][2], wb, v);
            v = fmaf(ppf_s[k][3], wc, v);
            pe1_s[k][tid] = fmaxf(v, 0.0f);
        }
    }
    __syncthreads();

    // pe layer 2 + gather xk/xv and build k/v tiles
    {
        float acc[KNN];
        float bb = __ldg(&b2[tid]);
#pragma unroll
        for (int k = 0; k < KNN; k++) acc[k] = bb;
        for (int j = 0; j < CF; j++) {
            float w = __ldg(&w2[j * CF + tid]);
#pragma unroll
            for (int k = 0; k < KNN; k++) acc[k] = fmaf(pe1_s[k][j], w, acc[k]);
        }
#pragma unroll
        for (int k = 0; k < KNN; k++) {
            const int jrow = idx_s[k];
            k_s[k][tid] = g_xk[jrow * CF + tid] + acc[k];
            v_s[k][tid] = g_xv[jrow * CF + tid] + acc[k];
        }
    }
    __syncthreads();

    // attention: thread = (head h, neighbor kk)
    {
        const int h  = tid >> 4;
        const int kk = tid & 15;
        float logit = 0.0f;
#pragma unroll
        for (int d = 0; d < DHD; d++)
            logit = fmaf(q_s[h * DHD + d], k_s[kk][h * DHD + d], logit);
        logit *= 0.25f;  // 1/sqrt(16)

        float m = logit;
#pragma unroll
        for (int s = 8; s >= 1; s >>= 1)
            m = fmaxf(m, __shfl_xor_sync(0xffffffffu, m, s, 16));
        float e = expf(logit - m);
        float ssum = e;
#pragma unroll
        for (int s = 8; s >= 1; s >>= 1)
            ssum += __shfl_xor_sync(0xffffffffu, ssum, s, 16);
        attn_s[tid] = e / ssum;
    }
    __syncthreads();

    // out[c] = sum_k attn[h][k] * v[k][c],  c = h*16 + d
    {
        float o = 0.0f;
        const int hb = tid & ~15;
#pragma unroll
        for (int k = 0; k < KNN; k++)
            o = fmaf(attn_s[hb + k], v_s[k][tid], o);
        o_s[tid] = o;
    }
    __syncthreads();

    // y = o @ Wo
    float y = 0.0f;
#pragma unroll
    for (int j = 0; j < CF; j++)
        y = fmaf(o_s[j], __ldg(&Wo[j * CF + tid]), y);

    // LayerNorm over 64 channels (biased var), residual, relu
    float s1 = y, s2 = y * y;
#pragma unroll
    for (int s = 16; s >= 1; s >>= 1) {
        s1 += __shfl_xor_sync(0xffffffffu, s1, s);
        s2 += __shfl_xor_sync(0xffffffffu, s2, s);
    }
    if ((tid & 31) == 0) {
        red_s[(tid >> 5) * 2 + 0] = s1;
        red_s[(tid >> 5) * 2 + 1] = s2;
    }
    __syncthreads();
    float S1 = red_s[0] + red_s[2];
    float S2 = red_s[1] + red_s[3];
    float mu  = S1 * (1.0f / 64.0f);
    float var = S2 * (1.0f / 64.0f) - mu * mu;
    float nrm = (y - mu) * rsqrtf(var + 1e-5f);
    float res = fmaf(nrm, __ldg(&ln_g[tid]), __ldg(&ln_b[tid])) + x[n * CF + tid];
    out[n * CF + tid] = fmaxf(res, 0.0f);
}

// ---------------- launch -----------------------------------------------------
extern "C" void kernel_launch(void* const* d_in, const int* in_sizes, int n_in,
                              void* d_out, int out_size) {
    (void)in_sizes; (void)n_in; (void)out_size;
    const float* p       = (const float*)d_in[0];
    const float* x       = (const float*)d_in[1];
    const float* normals = (const float*)d_in[2];
    const float* Wq      = (const float*)d_in[3];
    const float* Wk      = (const float*)d_in[4];
    const float* Wv      = (const float*)d_in[5];
    const float* Wo      = (const float*)d_in[6];
    const float* w1      = (const float*)d_in[7];
    const float* b1      = (const float*)d_in[8];
    const float* w2      = (const float*)d_in[9];
    const float* b2      = (const float*)d_in[10];
    const float* ln_g    = (const float*)d_in[11];
    const float* ln_b    = (const float*)d_in[12];
    float* out = (float*)d_out;

    knn_part_kernel<<<dim3(NPTS / 256, NCHUNK), 256>>>(p);
    knn_merge_kernel<<<NPTS / 256, 256>>>();
    qkv_gemm_kernel<<<dim3(NPTS / 64, 3), dim3(64, 4)>>>(x, Wq, Wk, Wv);
    fused_attn_kernel<<<NPTS, 64>>>(p, x, normals, Wo, w1, b1, w2, b2,
                                    ln_g, ln_b, out);
}

// round 2
// speedup vs baseline: 2.3044x; 2.3044x over previous
#include <cuda_runtime.h>
#include <math.h>

#define NPTS 8192
#define CF   64
#define NH   4
#define KNN  16
#define DHD  16
#define TILE 1024

#define FINF 3.402823466e38f

// ---------------- scratch (static device memory; no allocations) -------------
__device__ float g_xq[NPTS * CF];
__device__ float g_xk[NPTS * CF];
__device__ float g_xv[NPTS * CF];
__device__ int   g_idx[NPTS * KNN];

// ---------------- KNN: warp-cooperative exact top-16 -------------------------
// One warp per query. Top-16 entries distributed over lanes 0..15; threshold =
// warp-max over those entries. Insertions are warp-uniform (no divergence).
__global__ void __launch_bounds__(256)
knn_kernel(const float* __restrict__ p) {
    __shared__ float sx[TILE], sy[TILE], sz[TILE];
    const int lane = threadIdx.x & 31;
    const int warp = threadIdx.x >> 5;
    const int q    = blockIdx.x * 8 + warp;

    const float qx = p[3 * q + 0], qy = p[3 * q + 1], qz = p[3 * q + 2];

    float best_d = FINF;       // valid in lanes 0..15
    int   best_i = 0;
    float thr    = FINF;       // uniform across warp

    for (int tile = 0; tile < NPTS; tile += TILE) {
        __syncthreads();
        for (int f = threadIdx.x; f < TILE * 3; f += 256) {
            float v = p[tile * 3 + f];
            int j = f / 3, c = f - 3 * j;
            if (c == 0) sx[j] = v; else if (c == 1) sy[j] = v; else sz[j] = v;
        }
        __syncthreads();

        for (int j0 = 0; j0 < TILE; j0 += 32) {
            const int j = j0 + lane;
            float dx = qx - sx[j], dy = qy - sy[j], dz = qz - sz[j];
            float d = fmaf(dx, dx, fmaf(dy, dy, dz * dz));

            unsigned mask = __ballot_sync(0xffffffffu, d < thr);
            while (mask) {
                const int src = __ffs(mask) - 1;
                mask &= mask - 1;
                const float dn = __shfl_sync(0xffffffffu, d, src);
                if (dn < thr) {                      // uniform branch
                    // argmax over the 16 held entries
                    float v = (lane < 16) ? best_d : -FINF;
                    float m = v;
#pragma unroll
                    for (int s = 16; s >= 1; s >>= 1)
                        m = fmaxf(m, __shfl_xor_sync(0xffffffffu, m, s));
                    unsigned mb = __ballot_sync(0xffffffffu, (lane < 16) && (best_d == m));
                    const int maxlane = __ffs(mb) - 1;
                    if (lane == maxlane) { best_d = dn; best_i = tile + j0 + src; }
                    // recompute threshold
                    float v2 = (lane < 16) ? best_d : -FINF;
#pragma unroll
                    for (int s = 16; s >= 1; s >>= 1)
                        v2 = fmaxf(v2, __shfl_xor_sync(0xffffffffu, v2, s));
                    thr = v2;
                }
            }
        }
    }
    if (lane < KNN) g_idx[q * KNN + lane] = best_i;
}

// ---------------- xq/xk/xv = x @ {Wq,Wk,Wv} ---------------------------------
__global__ void __launch_bounds__(256)
qkv_gemm_kernel(const float* __restrict__ x,
                const float* __restrict__ Wq,
                const float* __restrict__ Wk,
                const float* __restrict__ Wv) {
    __shared__ __align__(16) float Ws[CF * CF];
    __shared__ __align__(16) float xs[CF * CF];
    const float* W = (blockIdx.y == 0) ? Wq : ((blockIdx.y == 1) ? Wk : Wv);
    float* out = (blockIdx.y == 0) ? g_xq : ((blockIdx.y == 1) ? g_xk : g_xv);

    const int row0 = blockIdx.x * 64;
    const int tid  = threadIdx.y * 64 + threadIdx.x;
    for (int f = tid; f < CF * CF; f += 256) {
        Ws[f] = W[f];
        xs[f] = x[row0 * CF + f];
    }
    __syncthreads();

    const int c  = threadIdx.x;
    const int r0 = threadIdx.y * 16;
    float acc[16];
#pragma unroll
    for (int r = 0; r < 16; r++) acc[r] = 0.0f;

    const float4* xsv = reinterpret_cast<const float4*>(xs);
    for (int j4 = 0; j4 < 16; j4++) {
        float w0 = Ws[(4 * j4 + 0) * CF + c];
        float w1 = Ws[(4 * j4 + 1) * CF + c];
        float w2 = Ws[(4 * j4 + 2) * CF + c];
        float w3 = Ws[(4 * j4 + 3) * CF + c];
#pragma unroll
        for (int r = 0; r < 16; r++) {
            float4 xv = xsv[(r0 + r) * 16 + j4];
            acc[r] = fmaf(xv.x, w0, acc[r]);
            acc[r] = fmaf(xv.y, w1, acc[r]);
            acc[r] = fmaf(xv.z, w2, acc[r]);
            acc[r] = fmaf(xv.w, w3, acc[r]);
        }
    }
#pragma unroll
    for (int r = 0; r < 16; r++) out[(row0 + r0 + r) * CF + c] = acc[r];
}

// ---------------- PPF angle helper ------------------------------------------
__device__ __forceinline__ float angle3(float ux, float uy, float uz,
                                        float vx, float vy, float vz) {
    float cx = uy * vz - uz * vy;
    float cy = uz * vx - ux * vz;
    float cz = ux * vy - uy * vx;
    float cn = sqrtf(cx * cx + cy * cy + cz * cz + 1e-9f);
    float dt = ux * vx + uy * vy + uz * vz;
    return atan2f(cn, dt);
}

// ---------------- Fused: PPF -> pe MLP -> attention -> Wo -> LN -> relu ------
__global__ void __launch_bounds__(64)
fused_attn_kernel(const float* __restrict__ p,
                  const float* __restrict__ x,
                  const float* __restrict__ normals,
                  const float* __restrict__ Wo,
                  const float* __restrict__ w1, const float* __restrict__ b1,
                  const float* __restrict__ w2, const float* __restrict__ b2,
                  const float* __restrict__ ln_g, const float* __restrict__ ln_b,
                  float* __restrict__ out) {
    const int n   = blockIdx.x;
    const int tid = threadIdx.x;

    __shared__ int   idx_s[KNN];
    __shared__ __align__(16) float ppf_s[KNN][4];
    __shared__ __align__(16) float pe1_s[KNN][CF];
    __shared__ __align__(16) float k_s[KNN][CF];
    __shared__ __align__(16) float v_s[KNN][CF];
    __shared__ __align__(16) float q_s[CF];
    __shared__ __align__(16) float o_s[CF];
    __shared__ float attn_s[NH * KNN];
    __shared__ float red_s[4];

    if (tid < KNN) idx_s[tid] = g_idx[n * KNN + tid];
    q_s[tid] = g_xq[n * CF + tid];
    __syncthreads();

    // PPF features: one thread per neighbor
    if (tid < KNN) {
        const int j = idx_s[tid];
        float px = p[3 * n], py = p[3 * n + 1], pz = p[3 * n + 2];
        float dx = p[3 * j] - px, dy = p[3 * j + 1] - py, dz = p[3 * j + 2] - pz;
        float ncx = normals[3 * n], ncy = normals[3 * n + 1], ncz = normals[3 * n + 2];
        float nrx = normals[3 * j], nry = normals[3 * j + 1], nrz = normals[3 * j + 2];
        ppf_s[tid][0] = angle3(ncx, ncy, ncz, dx, dy, dz);
        ppf_s[tid][1] = angle3(nrx, nry, nrz, dx, dy, dz);
        ppf_s[tid][2] = angle3(ncx, ncy, ncz, nrx, nry, nrz);
        ppf_s[tid][3] = sqrtf(dx * dx + dy * dy + dz * dz + 1e-9f);
    }
    __syncthreads();

    // pe layer 1: pe1[k][c] = relu(b1[c] + sum_j ppf[k][j] * w1[j][c])
    {
        float w0 = __ldg(&w1[0 * CF + tid]);
        float wa = __ldg(&w1[1 * CF + tid]);
        float wb = __ldg(&w1[2 * CF + tid]);
        float wc = __ldg(&w1[3 * CF + tid]);
        float bb = __ldg(&b1[tid]);
#pragma unroll
        for (int k = 0; k < KNN; k++) {
            float4 pf = *reinterpret_cast<const float4*>(&ppf_s[k][0]);
            float v = bb;
            v = fmaf(pf.x, w0, v);
            v = fmaf(pf.y, wa, v);
            v = fmaf(pf.z, wb, v);
            v = fmaf(pf.w, wc, v);
            pe1_s[k][tid] = fmaxf(v, 0.0f);
        }
    }
    __syncthreads();

    // pe layer 2 + gather xk/xv and build k/v tiles  (float4 broadcast LDS)
    {
        float acc[KNN];
        float bb = __ldg(&b2[tid]);
#pragma unroll
        for (int k = 0; k < KNN; k++) acc[k] = bb;
        const float4* pe1v = reinterpret_cast<const float4*>(&pe1_s[0][0]);
        for (int j4 = 0; j4 < 16; j4++) {
            float w0 = __ldg(&w2[(4 * j4 + 0) * CF + tid]);
            float wa = __ldg(&w2[(4 * j4 + 1) * CF + tid]);
            float wb = __ldg(&w2[(4 * j4 + 2) * CF + tid]);
            float wc = __ldg(&w2[(4 * j4 + 3) * CF + tid]);
#pragma unroll
            for (int k = 0; k < KNN; k++) {
                float4 pv = pe1v[k * 16 + j4];
                acc[k] = fmaf(pv.x, w0, acc[k]);
                acc[k] = fmaf(pv.y, wa, acc[k]);
                acc[k] = fmaf(pv.z, wb, acc[k]);
                acc[k] = fmaf(pv.w, wc, acc[k]);
            }
        }
#pragma unroll
        for (int k = 0; k < KNN; k++) {
            const int jrow = idx_s[k];
            k_s[k][tid] = g_xk[jrow * CF + tid] + acc[k];
            v_s[k][tid] = g_xv[jrow * CF + tid] + acc[k];
        }
    }
    __syncthreads();

    // attention: thread = (head h, neighbor kk)
    {
        const int h  = tid >> 4;
        const int kk = tid & 15;
        float logit = 0.0f;
        const float4* kv = reinterpret_cast<const float4*>(&k_s[kk][h * DHD]);
        const float4* qv = reinterpret_cast<const float4*>(&q_s[h * DHD]);
#pragma unroll
        for (int d4 = 0; d4 < 4; d4++) {
            float4 kq = kv[d4];
            float4 qq = qv[d4];
            logit = fmaf(qq.x, kq.x, logit);
            logit = fmaf(qq.y, kq.y, logit);
            logit = fmaf(qq.z, kq.z, logit);
            logit = fmaf(qq.w, kq.w, logit);
        }
        logit *= 0.25f;  // 1/sqrt(16)

        float m = logit;
#pragma unroll
        for (int s = 8; s >= 1; s >>= 1)
            m = fmaxf(m, __shfl_xor_sync(0xffffffffu, m, s, 16));
        float e = expf(logit - m);
        float ssum = e;
#pragma unroll
        for (int s = 8; s >= 1; s >>= 1)
            ssum += __shfl_xor_sync(0xffffffffu, ssum, s, 16);
        attn_s[tid] = e / ssum;
    }
    __syncthreads();

    // out[c] = sum_k attn[h][k] * v[k][c],  c = h*16 + d
    {
        float o = 0.0f;
        const int hb = tid & ~15;
#pragma unroll
        for (int k = 0; k < KNN; k++)
            o = fmaf(attn_s[hb + k], v_s[k][tid], o);
        o_s[tid] = o;
    }
    __syncthreads();

    // y = o @ Wo  (float4 broadcast LDS on o_s)
    float y = 0.0f;
    {
        const float4* ov = reinterpret_cast<const float4*>(o_s);
        for (int j4 = 0; j4 < 16; j4++) {
            float4 o4 = ov[j4];
            y = fmaf(o4.x, __ldg(&Wo[(4 * j4 + 0) * CF + tid]), y);
            y = fmaf(o4.y, __ldg(&Wo[(4 * j4 + 1) * CF + tid]), y);
            y = fmaf(o4.z, __ldg(&Wo[(4 * j4 + 2) * CF + tid]), y);
            y = fmaf(o4.w, __ldg(&Wo[(4 * j4 + 3) * CF + tid]), y);
        }
    }

    // LayerNorm over 64 channels (biased var), residual, relu
    float s1 = y, s2 = y * y;
#pragma unroll
    for (int s = 16; s >= 1; s >>= 1) {
        s1 += __shfl_xor_sync(0xffffffffu, s1, s);
        s2 += __shfl_xor_sync(0xffffffffu, s2, s);
    }
    if ((tid & 31) == 0) {
        red_s[(tid >> 5) * 2 + 0] = s1;
        red_s[(tid >> 5) * 2 + 1] = s2;
    }
    __syncthreads();
    float S1 = red_s[0] + red_s[2];
    float S2 = red_s[1] + red_s[3];
    float mu  = S1 * (1.0f / 64.0f);
    float var = S2 * (1.0f / 64.0f) - mu * mu;
    float nrm = (y - mu) * rsqrtf(var + 1e-5f);
    float res = fmaf(nrm, __ldg(&ln_g[tid]), __ldg(&ln_b[tid])) + x[n * CF + tid];
    out[n * CF + tid] = fmaxf(res, 0.0f);
}

// ---------------- launch -----------------------------------------------------
extern "C" void kernel_launch(void* const* d_in, const int* in_sizes, int n_in,
                              void* d_out, int out_size) {
    (void)in_sizes; (void)n_in; (void)out_size;
    const float* p       = (const float*)d_in[0];
    const float* x       = (const float*)d_in[1];
    const float* normals = (const float*)d_in[2];
    const float* Wq      = (const float*)d_in[3];
    const float* Wk      = (const float*)d_in[4];
    const float* Wv      = (const float*)d_in[5];
    const float* Wo      = (const float*)d_in[6];
    const float* w1      = (const float*)d_in[7];
    const float* b1      = (const float*)d_in[8];
    const float* w2      = (const float*)d_in[9];
    const float* b2      = (const float*)d_in[10];
    const float* ln_g    = (const float*)d_in[11];
    const float* ln_b    = (const float*)d_in[12];
    float* out = (float*)d_out;

    knn_kernel<<<NPTS / 8, 256>>>(p);
    qkv_gemm_kernel<<<dim3(NPTS / 64, 3), dim3(64, 4)>>>(x, Wq, Wk, Wv);
    fused_attn_kernel<<<NPTS, 64>>>(p, x, normals, Wo, w1, b1, w2, b2,
                                    ln_g, ln_b, out);
}

// round 3
// speedup vs baseline: 2.8856x; 1.2522x over previous
#include <cuda_runtime.h>
#include <math.h>

#define NPTS 8192
#define CF   64
#define NH   4
#define KNN  16
#define DHD  16
#define TILE 1024

#define FINF 3.402823466e38f

// ---------------- scratch (static device memory; no allocations) -------------
__device__ float g_xq[NPTS * CF];
__device__ float g_xk[NPTS * CF];
__device__ float g_xv[NPTS * CF];
__device__ int   g_idx[NPTS * KNN];

// ---------------- KNN: warp-cooperative exact top-16, vectorized -------------
// One warp per query. Top-16 distributed over lanes 0..15; threshold = warp max.
// Candidates packed as float4(x,y,z,|p|^2); ranking metric t = |p|^2 - 2 q.p
// (monotone in true distance). 4 candidates per lane per ballot.
__global__ void __launch_bounds__(256)
knn_kernel(const float* __restrict__ p) {
    __shared__ __align__(16) float4 s4[TILE];
    const int lane = threadIdx.x & 31;
    const int warp = threadIdx.x >> 5;
    const int q    = blockIdx.x * 8 + warp;

    const float qx = p[3 * q + 0], qy = p[3 * q + 1], qz = p[3 * q + 2];
    const float m2x = -2.0f * qx, m2y = -2.0f * qy, m2z = -2.0f * qz;

    float best_d = FINF;       // valid in lanes 0..15
    int   best_i = 0;
    float thr    = FINF;       // uniform across warp

    for (int tile = 0; tile < NPTS; tile += TILE) {
        __syncthreads();
        for (int j = threadIdx.x; j < TILE; j += 256) {
            float x = p[(tile + j) * 3 + 0];
            float y = p[(tile + j) * 3 + 1];
            float z = p[(tile + j) * 3 + 2];
            s4[j] = make_float4(x, y, z, fmaf(x, x, fmaf(y, y, z * z)));
        }
        __syncthreads();

        for (int j0 = 0; j0 < TILE; j0 += 128) {
            float4 a = s4[j0 + lane];
            float4 b = s4[j0 + 32 + lane];
            float4 c = s4[j0 + 64 + lane];
            float4 e = s4[j0 + 96 + lane];
            float t0 = fmaf(m2x, a.x, fmaf(m2y, a.y, fmaf(m2z, a.z, a.w)));
            float t1 = fmaf(m2x, b.x, fmaf(m2y, b.y, fmaf(m2z, b.z, b.w)));
            float t2 = fmaf(m2x, c.x, fmaf(m2y, c.y, fmaf(m2z, c.z, c.w)));
            float t3 = fmaf(m2x, e.x, fmaf(m2y, e.y, fmaf(m2z, e.z, e.w)));
            float tmin = fminf(fminf(t0, t1), fminf(t2, t3));

            if (__any_sync(0xffffffffu, tmin < thr)) {
                float tv[4] = {t0, t1, t2, t3};
#pragma unroll
                for (int u = 0; u < 4; u++) {
                    unsigned mask = __ballot_sync(0xffffffffu, tv[u] < thr);
                    while (mask) {
                        const int src = __ffs(mask) - 1;
                        mask &= mask - 1;
                        const float dn = __shfl_sync(0xffffffffu, tv[u], src);
                        if (dn < thr) {                      // uniform branch
                            // argmax over the 16 held entries
                            float m = (lane < 16) ? best_d : -FINF;
#pragma unroll
                            for (int s = 16; s >= 1; s >>= 1)
                                m = fmaxf(m, __shfl_xor_sync(0xffffffffu, m, s));
                            unsigned mb = __ballot_sync(0xffffffffu,
                                              (lane < 16) && (best_d == m));
                            const int maxlane = __ffs(mb) - 1;
                            if (lane == maxlane) {
                                best_d = dn;
                                best_i = tile + j0 + u * 32 + src;
                            }
                            float v2 = (lane < 16) ? best_d : -FINF;
#pragma unroll
                            for (int s = 16; s >= 1; s >>= 1)
                                v2 = fmaxf(v2, __shfl_xor_sync(0xffffffffu, v2, s));
                            thr = v2;
                        }
                    }
                }
            }
        }
    }
    if (lane < KNN) g_idx[q * KNN + lane] = best_i;
}

// ---------------- xq/xk/xv = x @ {Wq,Wk,Wv} ---------------------------------
__global__ void __launch_bounds__(256)
qkv_gemm_kernel(const float* __restrict__ x,
                const float* __restrict__ Wq,
                const float* __restrict__ Wk,
                const float* __restrict__ Wv) {
    __shared__ __align__(16) float Ws[CF * CF];
    __shared__ __align__(16) float xs[CF * CF];
    const float* W = (blockIdx.y == 0) ? Wq : ((blockIdx.y == 1) ? Wk : Wv);
    float* out = (blockIdx.y == 0) ? g_xq : ((blockIdx.y == 1) ? g_xk : g_xv);

    const int row0 = blockIdx.x * 64;
    const int tid  = threadIdx.y * 64 + threadIdx.x;
    for (int f = tid; f < CF * CF; f += 256) {
        Ws[f] = W[f];
        xs[f] = x[row0 * CF + f];
    }
    __syncthreads();

    const int c  = threadIdx.x;
    const int r0 = threadIdx.y * 16;
    float acc[16];
#pragma unroll
    for (int r = 0; r < 16; r++) acc[r] = 0.0f;

    const float4* xsv = reinterpret_cast<const float4*>(xs);
    for (int j4 = 0; j4 < 16; j4++) {
        float w0 = Ws[(4 * j4 + 0) * CF + c];
        float w1 = Ws[(4 * j4 + 1) * CF + c];
        float w2 = Ws[(4 * j4 + 2) * CF + c];
        float w3 = Ws[(4 * j4 + 3) * CF + c];
#pragma unroll
        for (int r = 0; r < 16; r++) {
            float4 xv = xsv[(r0 + r) * 16 + j4];
            acc[r] = fmaf(xv.x, w0, acc[r]);
            acc[r] = fmaf(xv.y, w1, acc[r]);
            acc[r] = fmaf(xv.z, w2, acc[r]);
            acc[r] = fmaf(xv.w, w3, acc[r]);
        }
    }
#pragma unroll
    for (int r = 0; r < 16; r++) out[(row0 + r0 + r) * CF + c] = acc[r];
}

// ---------------- PPF angle helper ------------------------------------------
__device__ __forceinline__ float angle3(float ux, float uy, float uz,
                                        float vx, float vy, float vz) {
    float cx = uy * vz - uz * vy;
    float cy = uz * vx - ux * vz;
    float cz = ux * vy - uy * vx;
    float cn = sqrtf(cx * cx + cy * cy + cz * cz + 1e-9f);
    float dt = ux * vx + uy * vy + uz * vz;
    return atan2f(cn, dt);
}

// ---------------- Fused: PPF -> pe MLP -> attention -> Wo -> LN -> relu ------
__global__ void __launch_bounds__(64)
fused_attn_kernel(const float* __restrict__ p,
                  const float* __restrict__ x,
                  const float* __restrict__ normals,
                  const float* __restrict__ Wo,
                  const float* __restrict__ w1, const float* __restrict__ b1,
                  const float* __restrict__ w2, const float* __restrict__ b2,
                  const float* __restrict__ ln_g, const float* __restrict__ ln_b,
                  float* __restrict__ out) {
    const int n   = blockIdx.x;
    const int tid = threadIdx.x;

    __shared__ int   idx_s[KNN];
    __shared__ __align__(16) float ppf_s[KNN][4];
    __shared__ __align__(16) float pe1_s[KNN][CF];
    __shared__ __align__(16) float k_s[KNN][CF];
    __shared__ __align__(16) float v_s[KNN][CF];
    __shared__ __align__(16) float q_s[CF];
    __shared__ __align__(16) float o_s[CF];
    __shared__ float attn_s[NH * KNN];
    __shared__ float red_s[4];

    if (tid < KNN) idx_s[tid] = g_idx[n * KNN + tid];
    q_s[tid] = g_xq[n * CF + tid];
    __syncthreads();

    // PPF features: one thread per neighbor
    if (tid < KNN) {
        const int j = idx_s[tid];
        float px = p[3 * n], py = p[3 * n + 1], pz = p[3 * n + 2];
        float dx = p[3 * j] - px, dy = p[3 * j + 1] - py, dz = p[3 * j + 2] - pz;
        float ncx = normals[3 * n], ncy = normals[3 * n + 1], ncz = normals[3 * n + 2];
        float nrx = normals[3 * j], nry = normals[3 * j + 1], nrz = normals[3 * j + 2];
        ppf_s[tid][0] = angle3(ncx, ncy, ncz, dx, dy, dz);
        ppf_s[tid][1] = angle3(nrx, nry, nrz, dx, dy, dz);
        ppf_s[tid][2] = angle3(ncx, ncy, ncz, nrx, nry, nrz);
        ppf_s[tid][3] = sqrtf(dx * dx + dy * dy + dz * dz + 1e-9f);
    }
    __syncthreads();

    // pe layer 1: pe1[k][c] = relu(b1[c] + sum_j ppf[k][j] * w1[j][c])
    {
        float w0 = __ldg(&w1[0 * CF + tid]);
        float wa = __ldg(&w1[1 * CF + tid]);
        float wb = __ldg(&w1[2 * CF + tid]);
        float wc = __ldg(&w1[3 * CF + tid]);
        float bb = __ldg(&b1[tid]);
#pragma unroll
        for (int k = 0; k < KNN; k++) {
            float4 pf = *reinterpret_cast<const float4*>(&ppf_s[k][0]);
            float v = bb;
            v = fmaf(pf.x, w0, v);
            v = fmaf(pf.y, wa, v);
            v = fmaf(pf.z, wb, v);
            v = fmaf(pf.w, wc, v);
            pe1_s[k][tid] = fmaxf(v, 0.0f);
        }
    }
    __syncthreads();

    // pe layer 2 + gather xk/xv and build k/v tiles  (float4 broadcast LDS)
    {
        float acc[KNN];
        float bb = __ldg(&b2[tid]);
#pragma unroll
        for (int k = 0; k < KNN; k++) acc[k] = bb;
        const float4* pe1v = reinterpret_cast<const float4*>(&pe1_s[0][0]);
        for (int j4 = 0; j4 < 16; j4++) {
            float w0 = __ldg(&w2[(4 * j4 + 0) * CF + tid]);
            float wa = __ldg(&w2[(4 * j4 + 1) * CF + tid]);
            float wb = __ldg(&w2[(4 * j4 + 2) * CF + tid]);
            float wc = __ldg(&w2[(4 * j4 + 3) * CF + tid]);
#pragma unroll
            for (int k = 0; k < KNN; k++) {
                float4 pv = pe1v[k * 16 + j4];
                acc[k] = fmaf(pv.x, w0, acc[k]);
                acc[k] = fmaf(pv.y, wa, acc[k]);
                acc[k] = fmaf(pv.z, wb, acc[k]);
                acc[k] = fmaf(pv.w, wc, acc[k]);
            }
        }
#pragma unroll
        for (int k = 0; k < KNN; k++) {
            const int jrow = idx_s[k];
            k_s[k][tid] = g_xk[jrow * CF + tid] + acc[k];
            v_s[k][tid] = g_xv[jrow * CF + tid] + acc[k];
        }
    }
    __syncthreads();

    // attention: thread = (head h, neighbor kk)
    {
        const int h  = tid >> 4;
        const int kk = tid & 15;
        float logit = 0.0f;
        const float4* kv = reinterpret_cast<const float4*>(&k_s[kk][h * DHD]);
        const float4* qv = reinterpret_cast<const float4*>(&q_s[h * DHD]);
#pragma unroll
        for (int d4 = 0; d4 < 4; d4++) {
            float4 kq = kv[d4];
            float4 qq = qv[d4];
            logit = fmaf(qq.x, kq.x, logit);
            logit = fmaf(qq.y, kq.y, logit);
            logit = fmaf(qq.z, kq.z, logit);
            logit = fmaf(qq.w, kq.w, logit);
        }
        logit *= 0.25f;  // 1/sqrt(16)

        float m = logit;
#pragma unroll
        for (int s = 8; s >= 1; s >>= 1)
            m = fmaxf(m, __shfl_xor_sync(0xffffffffu, m, s, 16));
        float e = expf(logit - m);
        float ssum = e;
#pragma unroll
        for (int s = 8; s >= 1; s >>= 1)
            ssum += __shfl_xor_sync(0xffffffffu, ssum, s, 16);
        attn_s[tid] = e / ssum;
    }
    __syncthreads();

    // out[c] = sum_k attn[h][k] * v[k][c],  c = h*16 + d
    {
        float o = 0.0f;
        const int hb = tid & ~15;
#pragma unroll
        for (int k = 0; k < KNN; k++)
            o = fmaf(attn_s[hb + k], v_s[k][tid], o);
        o_s[tid] = o;
    }
    __syncthreads();

    // y = o @ Wo  (float4 broadcast LDS on o_s)
    float y = 0.0f;
    {
        const float4* ov = reinterpret_cast<const float4*>(o_s);
        for (int j4 = 0; j4 < 16; j4++) {
            float4 o4 = ov[j4];
            y = fmaf(o4.x, __ldg(&Wo[(4 * j4 + 0) * CF + tid]), y);
            y = fmaf(o4.y, __ldg(&Wo[(4 * j4 + 1) * CF + tid]), y);
            y = fmaf(o4.z, __ldg(&Wo[(4 * j4 + 2) * CF + tid]), y);
            y = fmaf(o4.w, __ldg(&Wo[(4 * j4 + 3) * CF + tid]), y);
        }
    }

    // LayerNorm over 64 channels (biased var), residual, relu
    float s1 = y, s2 = y * y;
#pragma unroll
    for (int s = 16; s >= 1; s >>= 1) {
        s1 += __shfl_xor_sync(0xffffffffu, s1, s);
        s2 += __shfl_xor_sync(0xffffffffu, s2, s);
    }
    if ((tid & 31) == 0) {
        red_s[(tid >> 5) * 2 + 0] = s1;
        red_s[(tid >> 5) * 2 + 1] = s2;
    }
    __syncthreads();
    float S1 = red_s[0] + red_s[2];
    float S2 = red_s[1] + red_s[3];
    float mu  = S1 * (1.0f / 64.0f);
    float var = S2 * (1.0f / 64.0f) - mu * mu;
    float nrm = (y - mu) * rsqrtf(var + 1e-5f);
    float res = fmaf(nrm, __ldg(&ln_g[tid]), __ldg(&ln_b[tid])) + x[n * CF + tid];
    out[n * CF + tid] = fmaxf(res, 0.0f);
}

// ---------------- launch -----------------------------------------------------
extern "C" void kernel_launch(void* const* d_in, const int* in_sizes, int n_in,
                              void* d_out, int out_size) {
    (void)in_sizes; (void)n_in; (void)out_size;
    const float* p       = (const float*)d_in[0];
    const float* x       = (const float*)d_in[1];
    const float* normals = (const float*)d_in[2];
    const float* Wq      = (const float*)d_in[3];
    const float* Wk      = (const float*)d_in[4];
    const float* Wv      = (const float*)d_in[5];
    const float* Wo      = (const float*)d_in[6];
    const float* w1      = (const float*)d_in[7];
    const float* b1      = (const float*)d_in[8];
    const float* w2      = (const float*)d_in[9];
    const float* b2      = (const float*)d_in[10];
    const float* ln_g    = (const float*)d_in[11];
    const float* ln_b    = (const float*)d_in[12];
    float* out = (float*)d_out;

    knn_kernel<<<NPTS / 8, 256>>>(p);
    qkv_gemm_kernel<<<dim3(NPTS / 64, 3), dim3(64, 4)>>>(x, Wq, Wk, Wv);
    fused_attn_kernel<<<NPTS, 64>>>(p, x, normals, Wo, w1, b1, w2, b2,
                                    ln_g, ln_b, out);
}

// round 4
// speedup vs baseline: 3.4147x; 1.1834x over previous
#include <cuda_runtime.h>
#include <math.h>

#define NPTS 8192
#define CF   64
#define NH   4
#define KNN  16
#define DHD  16
#define TILE 1024

#define FINF 3.402823466e38f
#define FULLM 0xffffffffu

// ---------------- scratch (static device memory; no allocations) -------------
__device__ float g_xq[NPTS * CF];
__device__ float g_xk[NPTS * CF];
__device__ float g_xv[NPTS * CF];
__device__ int   g_idx[NPTS * KNN];

// ---------------- KNN: warp-cooperative, 2 queries/warp, sorted top-16 -------
// Lanes 0..15 hold query A's top-16 sorted ascending; lanes 16..31 hold B's.
// Threshold = lane 15 / lane 31 value. Insert = rank-ballot + shfl_up shift.
// Ranking metric t = |p|^2 - 2 q.p (monotone in true squared distance).
__global__ void __launch_bounds__(256)
knn_kernel(const float* __restrict__ p) {
    __shared__ __align__(16) float4 s4[TILE];
    const int lane  = threadIdx.x & 31;
    const int warp  = threadIdx.x >> 5;
    const int qbase = (blockIdx.x * 8 + warp) * 2;

    const float aX = -2.0f * p[3 * qbase + 0];
    const float aY = -2.0f * p[3 * qbase + 1];
    const float aZ = -2.0f * p[3 * qbase + 2];
    const float bX = -2.0f * p[3 * qbase + 3];
    const float bY = -2.0f * p[3 * qbase + 4];
    const float bZ = -2.0f * p[3 * qbase + 5];

    float best_d = FINF;   // sorted ascending within each 16-lane segment
    int   best_i = 0;
    float thrA = FINF, thrB = FINF;

    for (int tile = 0; tile < NPTS; tile += TILE) {
        __syncthreads();
        for (int j = threadIdx.x; j < TILE; j += 256) {
            float x = p[(tile + j) * 3 + 0];
            float y = p[(tile + j) * 3 + 1];
            float z = p[(tile + j) * 3 + 2];
            s4[j] = make_float4(x, y, z, fmaf(x, x, fmaf(y, y, z * z)));
        }
        __syncthreads();

        for (int j0 = 0; j0 < TILE; j0 += 128) {
            float4 c0 = s4[j0 + lane];
            float4 c1 = s4[j0 + 32 + lane];
            float4 c2 = s4[j0 + 64 + lane];
            float4 c3 = s4[j0 + 96 + lane];

            float tA[4], tB[4];
            tA[0] = fmaf(aX, c0.x, fmaf(aY, c0.y, fmaf(aZ, c0.z, c0.w)));
            tA[1] = fmaf(aX, c1.x, fmaf(aY, c1.y, fmaf(aZ, c1.z, c1.w)));
            tA[2] = fmaf(aX, c2.x, fmaf(aY, c2.y, fmaf(aZ, c2.z, c2.w)));
            tA[3] = fmaf(aX, c3.x, fmaf(aY, c3.y, fmaf(aZ, c3.z, c3.w)));
            tB[0] = fmaf(bX, c0.x, fmaf(bY, c0.y, fmaf(bZ, c0.z, c0.w)));
            tB[1] = fmaf(bX, c1.x, fmaf(bY, c1.y, fmaf(bZ, c1.z, c1.w)));
            tB[2] = fmaf(bX, c2.x, fmaf(bY, c2.y, fmaf(bZ, c2.z, c2.w)));
            tB[3] = fmaf(bX, c3.x, fmaf(bY, c3.y, fmaf(bZ, c3.z, c3.w)));

            float mA = fminf(fminf(tA[0], tA[1]), fminf(tA[2], tA[3]));
            float mB = fminf(fminf(tB[0], tB[1]), fminf(tB[2], tB[3]));

            if (__any_sync(FULLM, (mA < thrA) | (mB < thrB))) {
                // ---- query A events (segment lanes 0..15) ----
#pragma unroll
                for (int u = 0; u < 4; u++) {
                    unsigned mask = __ballot_sync(FULLM, tA[u] < thrA);
                    while (mask) {
                        const int src = __ffs(mask) - 1;
                        mask &= mask - 1;
                        const float dn = __shfl_sync(FULLM, tA[u], src);
                        if (dn < thrA) {
                            unsigned lt = __ballot_sync(FULLM, best_d < dn);
                            const int r = __popc(lt & 0xFFFFu);
                            float pd = __shfl_up_sync(FULLM, best_d, 1);
                            int   pi = __shfl_up_sync(FULLM, best_i, 1);
                            if (lane < 16) {
                                if (lane == r)      { best_d = dn; best_i = tile + j0 + u * 32 + src; }
                                else if (lane > r)  { best_d = pd; best_i = pi; }
                            }
                            thrA = __shfl_sync(FULLM, best_d, 15);
                        }
                    }
                }
                // ---- query B events (segment lanes 16..31) ----
#pragma unroll
                for (int u = 0; u < 4; u++) {
                    unsigned mask = __ballot_sync(FULLM, tB[u] < thrB);
                    while (mask) {
                        const int src = __ffs(mask) - 1;
                        mask &= mask - 1;
                        const float dn = __shfl_sync(FULLM, tB[u], src);
                        if (dn < thrB) {
                            unsigned lt = __ballot_sync(FULLM, best_d < dn);
                            const int r = __popc(lt >> 16);
                            float pd = __shfl_up_sync(FULLM, best_d, 1);
                            int   pi = __shfl_up_sync(FULLM, best_i, 1);
                            const int pos = lane - 16;
                            if (pos >= 0) {
                                if (pos == r)      { best_d = dn; best_i = tile + j0 + u * 32 + src; }
                                else if (pos > r)  { best_d = pd; best_i = pi; }
                            }
                            thrB = __shfl_sync(FULLM, best_d, 31);
                        }
                    }
                }
            }
        }
    }
    const int q = qbase + (lane >> 4);
    g_idx[q * KNN + (lane & 15)] = best_i;
}

// ---------------- xq/xk/xv = x @ {Wq,Wk,Wv} ---------------------------------
__global__ void __launch_bounds__(256)
qkv_gemm_kernel(const float* __restrict__ x,
                const float* __restrict__ Wq,
                const float* __restrict__ Wk,
                const float* __restrict__ Wv) {
    __shared__ __align__(16) float Ws[CF * CF];
    __shared__ __align__(16) float xs[CF * CF];
    const float* W = (blockIdx.y == 0) ? Wq : ((blockIdx.y == 1) ? Wk : Wv);
    float* out = (blockIdx.y == 0) ? g_xq : ((blockIdx.y == 1) ? g_xk : g_xv);

    const int row0 = blockIdx.x * 64;
    const int tid  = threadIdx.y * 64 + threadIdx.x;
    for (int f = tid; f < CF * CF; f += 256) {
        Ws[f] = W[f];
        xs[f] = x[row0 * CF + f];
    }
    __syncthreads();

    const int c  = threadIdx.x;
    const int r0 = threadIdx.y * 16;
    float acc[16];
#pragma unroll
    for (int r = 0; r < 16; r++) acc[r] = 0.0f;

    const float4* xsv = reinterpret_cast<const float4*>(xs);
    for (int j4 = 0; j4 < 16; j4++) {
        float w0 = Ws[(4 * j4 + 0) * CF + c];
        float w1 = Ws[(4 * j4 + 1) * CF + c];
        float w2 = Ws[(4 * j4 + 2) * CF + c];
        float w3 = Ws[(4 * j4 + 3) * CF + c];
#pragma unroll
        for (int r = 0; r < 16; r++) {
            float4 xv = xsv[(r0 + r) * 16 + j4];
            acc[r] = fmaf(xv.x, w0, acc[r]);
            acc[r] = fmaf(xv.y, w1, acc[r]);
            acc[r] = fmaf(xv.z, w2, acc[r]);
            acc[r] = fmaf(xv.w, w3, acc[r]);
        }
    }
#pragma unroll
    for (int r = 0; r < 16; r++) out[(row0 + r0 + r) * CF + c] = acc[r];
}

// ---------------- PPF angle helper ------------------------------------------
__device__ __forceinline__ float angle3(float ux, float uy, float uz,
                                        float vx, float vy, float vz) {
    float cx = uy * vz - uz * vy;
    float cy = uz * vx - ux * vz;
    float cz = ux * vy - uy * vx;
    float cn = sqrtf(cx * cx + cy * cy + cz * cz + 1e-9f);
    float dt = ux * vx + uy * vy + uz * vz;
    return atan2f(cn, dt);
}

// ---------------- Fused: PPF -> pe MLP -> attention -> Wo -> LN -> relu ------
__global__ void __launch_bounds__(64)
fused_attn_kernel(const float* __restrict__ p,
                  const float* __restrict__ x,
                  const float* __restrict__ normals,
                  const float* __restrict__ Wo,
                  const float* __restrict__ w1, const float* __restrict__ b1,
                  const float* __restrict__ w2, const float* __restrict__ b2,
                  const float* __restrict__ ln_g, const float* __restrict__ ln_b,
                  float* __restrict__ out) {
    const int n   = blockIdx.x;
    const int tid = threadIdx.x;

    __shared__ int   idx_s[KNN];
    __shared__ __align__(16) float ppf_s[KNN][4];
    __shared__ __align__(16) float pe1_s[KNN][CF];
    __shared__ __align__(16) float k_s[KNN][CF];
    __shared__ __align__(16) float v_s[KNN][CF];
    __shared__ __align__(16) float q_s[CF];
    __shared__ __align__(16) float o_s[CF];
    __shared__ float attn_s[NH * KNN];
    __shared__ float red_s[4];

    if (tid < KNN) idx_s[tid] = g_idx[n * KNN + tid];
    q_s[tid] = g_xq[n * CF + tid];
    __syncthreads();

    // PPF features: one thread per neighbor
    if (tid < KNN) {
        const int j = idx_s[tid];
        float px = p[3 * n], py = p[3 * n + 1], pz = p[3 * n + 2];
        float dx = p[3 * j] - px, dy = p[3 * j + 1] - py, dz = p[3 * j + 2] - pz;
        float ncx = normals[3 * n], ncy = normals[3 * n + 1], ncz = normals[3 * n + 2];
        float nrx = normals[3 * j], nry = normals[3 * j + 1], nrz = normals[3 * j + 2];
        ppf_s[tid][0] = angle3(ncx, ncy, ncz, dx, dy, dz);
        ppf_s[tid][1] = angle3(nrx, nry, nrz, dx, dy, dz);
        ppf_s[tid][2] = angle3(ncx, ncy, ncz, nrx, nry, nrz);
        ppf_s[tid][3] = sqrtf(dx * dx + dy * dy + dz * dz + 1e-9f);
    }
    __syncthreads();

    // pe layer 1: pe1[k][c] = relu(b1[c] + sum_j ppf[k][j] * w1[j][c])
    {
        float w0 = __ldg(&w1[0 * CF + tid]);
        float wa = __ldg(&w1[1 * CF + tid]);
        float wb = __ldg(&w1[2 * CF + tid]);
        float wc = __ldg(&w1[3 * CF + tid]);
        float bb = __ldg(&b1[tid]);
#pragma unroll
        for (int k = 0; k < KNN; k++) {
            float4 pf = *reinterpret_cast<const float4*>(&ppf_s[k][0]);
            float v = bb;
            v = fmaf(pf.x, w0, v);
            v = fmaf(pf.y, wa, v);
            v = fmaf(pf.z, wb, v);
            v = fmaf(pf.w, wc, v);
            pe1_s[k][tid] = fmaxf(v, 0.0f);
        }
    }
    __syncthreads();

    // pe layer 2 + gather xk/xv and build k/v tiles  (float4 broadcast LDS)
    {
        float acc[KNN];
        float bb = __ldg(&b2[tid]);
#pragma unroll
        for (int k = 0; k < KNN; k++) acc[k] = bb;
        const float4* pe1v = reinterpret_cast<const float4*>(&pe1_s[0][0]);
        for (int j4 = 0; j4 < 16; j4++) {
            float w0 = __ldg(&w2[(4 * j4 + 0) * CF + tid]);
            float wa = __ldg(&w2[(4 * j4 + 1) * CF + tid]);
            float wb = __ldg(&w2[(4 * j4 + 2) * CF + tid]);
            float wc = __ldg(&w2[(4 * j4 + 3) * CF + tid]);
#pragma unroll
            for (int k = 0; k < KNN; k++) {
                float4 pv = pe1v[k * 16 + j4];
                acc[k] = fmaf(pv.x, w0, acc[k]);
                acc[k] = fmaf(pv.y, wa, acc[k]);
                acc[k] = fmaf(pv.z, wb, acc[k]);
                acc[k] = fmaf(pv.w, wc, acc[k]);
            }
        }
#pragma unroll
        for (int k = 0; k < KNN; k++) {
            const int jrow = idx_s[k];
            k_s[k][tid] = g_xk[jrow * CF + tid] + acc[k];
            v_s[k][tid] = g_xv[jrow * CF + tid] + acc[k];
        }
    }
    __syncthreads();

    // attention: thread = (head h, neighbor kk)
    {
        const int h  = tid >> 4;
        const int kk = tid & 15;
        float logit = 0.0f;
        const float4* kv = reinterpret_cast<const float4*>(&k_s[kk][h * DHD]);
        const float4* qv = reinterpret_cast<const float4*>(&q_s[h * DHD]);
#pragma unroll
        for (int d4 = 0; d4 < 4; d4++) {
            float4 kq = kv[d4];
            float4 qq = qv[d4];
            logit = fmaf(qq.x, kq.x, logit);
            logit = fmaf(qq.y, kq.y, logit);
            logit = fmaf(qq.z, kq.z, logit);
            logit = fmaf(qq.w, kq.w, logit);
        }
        logit *= 0.25f;  // 1/sqrt(16)

        float m = logit;
#pragma unroll
        for (int s = 8; s >= 1; s >>= 1)
            m = fmaxf(m, __shfl_xor_sync(0xffffffffu, m, s, 16));
        float e = expf(logit - m);
        float ssum = e;
#pragma unroll
        for (int s = 8; s >= 1; s >>= 1)
            ssum += __shfl_xor_sync(0xffffffffu, ssum, s, 16);
        attn_s[tid] = e / ssum;
    }
    __syncthreads();

    // out[c] = sum_k attn[h][k] * v[k][c],  c = h*16 + d
    {
        float o = 0.0f;
        const int hb = tid & ~15;
#pragma unroll
        for (int k = 0; k < KNN; k++)
            o = fmaf(attn_s[hb + k], v_s[k][tid], o);
        o_s[tid] = o;
    }
    __syncthreads();

    // y = o @ Wo  (float4 broadcast LDS on o_s)
    float y = 0.0f;
    {
        const float4* ov = reinterpret_cast<const float4*>(o_s);
        for (int j4 = 0; j4 < 16; j4++) {
            float4 o4 = ov[j4];
            y = fmaf(o4.x, __ldg(&Wo[(4 * j4 + 0) * CF + tid]), y);
            y = fmaf(o4.y, __ldg(&Wo[(4 * j4 + 1) * CF + tid]), y);
            y = fmaf(o4.z, __ldg(&Wo[(4 * j4 + 2) * CF + tid]), y);
            y = fmaf(o4.w, __ldg(&Wo[(4 * j4 + 3) * CF + tid]), y);
        }
    }

    // LayerNorm over 64 channels (biased var), residual, relu
    float s1 = y, s2 = y * y;
#pragma unroll
    for (int s = 16; s >= 1; s >>= 1) {
        s1 += __shfl_xor_sync(0xffffffffu, s1, s);
        s2 += __shfl_xor_sync(0xffffffffu, s2, s);
    }
    if ((tid & 31) == 0) {
        red_s[(tid >> 5) * 2 + 0] = s1;
        red_s[(tid >> 5) * 2 + 1] = s2;
    }
    __syncthreads();
    float S1 = red_s[0] + red_s[2];
    float S2 = red_s[1] + red_s[3];
    float mu  = S1 * (1.0f / 64.0f);
    float var = S2 * (1.0f / 64.0f) - mu * mu;
    float nrm = (y - mu) * rsqrtf(var + 1e-5f);
    float res = fmaf(nrm, __ldg(&ln_g[tid]), __ldg(&ln_b[tid])) + x[n * CF + tid];
    out[n * CF + tid] = fmaxf(res, 0.0f);
}

// ---------------- launch -----------------------------------------------------
extern "C" void kernel_launch(void* const* d_in, const int* in_sizes, int n_in,
                              void* d_out, int out_size) {
    (void)in_sizes; (void)n_in; (void)out_size;
    const float* p       = (const float*)d_in[0];
    const float* x       = (const float*)d_in[1];
    const float* normals = (const float*)d_in[2];
    const float* Wq      = (const float*)d_in[3];
    const float* Wk      = (const float*)d_in[4];
    const float* Wv      = (const float*)d_in[5];
    const float* Wo      = (const float*)d_in[6];
    const float* w1      = (const float*)d_in[7];
    const float* b1      = (const float*)d_in[8];
    const float* w2      = (const float*)d_in[9];
    const float* b2      = (const float*)d_in[10];
    const float* ln_g    = (const float*)d_in[11];
    const float* ln_b    = (const float*)d_in[12];
    float* out = (float*)d_out;

    knn_kernel<<<NPTS / 16, 256>>>(p);
    qkv_gemm_kernel<<<dim3(NPTS / 64, 3), dim3(64, 4)>>>(x, Wq, Wk, Wv);
    fused_attn_kernel<<<NPTS, 64>>>(p, x, normals, Wo, w1, b1, w2, b2,
                                    ln_g, ln_b, out);
}